// round 3
// baseline (speedup 1.0000x reference)
#include <cuda_runtime.h>

#define NN 524288
#define EE 4194304
#define BB 4096
#define HH 32
#define KK 30
#define CAP 512
#define EPSF 1e-5f
#define NBLK 2048          // NN/256

// ---------------- scratch (device globals; no allocation allowed) ----------
__device__ int   g_deg[NN];
__device__ float g_dinv[NN];
__device__ float g_ha[(size_t)NN * HH];   // h' ping
__device__ float g_hb[(size_t)NN * HH];   // h' pong
__device__ float g_x[(size_t)NN * HH];    // final activations
__device__ int   g_rowstart[NN + 1];
__device__ int   g_cursor[NN];
__device__ int   g_csrsrc[EE];
__device__ unsigned long long g_lbstate[NBLK];
__device__ int   g_start2[BB + 1];
__device__ float g_pooled[(size_t)BB * KK * HH];

// ---------------- setup -----------------------------------------------------
__global__ void k_zero() {
    int i = blockIdx.x * 256 + threadIdx.x;
    g_deg[i] = 0;
    if (i < NBLK) g_lbstate[i] = 0ULL;
}

// in-degree histogram + graph-boundary detection (batch is sorted)
__global__ void k_degb(const int* __restrict__ dst, const int* __restrict__ batch) {
    int i = blockIdx.x * 256 + threadIdx.x;   // grid covers EE
    atomicAdd(&g_deg[dst[i]], 1);
    if (i < NN) {
        int b1 = batch[i];
        int b0 = (i > 0) ? batch[i - 1] : -1;
        for (int b = b0 + 1; b <= b1; b++) g_start2[b] = i;
        if (i == NN - 1)
            for (int b = b1 + 1; b <= BB; b++) g_start2[b] = NN;
    }
}

// single-pass decoupled-lookback exclusive scan of g_deg -> rowstart/cursor,
// also computes dinv.
__global__ void __launch_bounds__(256) k_scanlb() {
    __shared__ int s[256];
    __shared__ int sbase;
    int b = blockIdx.x, t = threadIdx.x;
    int i = b * 256 + t;
    int d = g_deg[i];
    g_dinv[i] = rsqrtf((float)d + 1.0f);
    s[t] = d;
    __syncthreads();
    for (int off = 1; off < 256; off <<= 1) {
        int v = (t >= off) ? s[t - off] : 0;
        __syncthreads();
        s[t] += v;
        __syncthreads();
    }
    int total = s[255];
    if (t == 0) {
        if (b == 0) {
            atomicExch(&g_lbstate[0], (2ULL << 32) | (unsigned)total);
            sbase = 0;
        } else {
            atomicExch(&g_lbstate[b], (1ULL << 32) | (unsigned)total);
            int excl = 0;
            int j = b - 1;
            while (true) {
                unsigned long long v;
                do { v = atomicAdd(&g_lbstate[j], 0ULL); } while ((v >> 32) == 0ULL);
                excl += (int)(unsigned)v;
                if ((v >> 32) == 2ULL) break;
                j--;
            }
            atomicExch(&g_lbstate[b], (2ULL << 32) | (unsigned)(excl + total));
            sbase = excl;
        }
    }
    __syncthreads();
    int ex = sbase + s[t] - d;
    g_rowstart[i] = ex;
    g_cursor[i] = ex;
    if (i == NN - 1) g_rowstart[NN] = EE;
}

// ---------------- CSR fill: src index only ----------------------------------
__global__ void k_fill(const int* __restrict__ src, const int* __restrict__ dst) {
    int e = blockIdx.x * 256 + threadIdx.x;   // grid covers EE
    int s = src[e], d = dst[e];
    int pos = atomicAdd(&g_cursor[d], 1);
    g_csrsrc[pos] = s;
}

// ---------------- layer 0: h0' = (emb[xz] @ W0) * dinv ----------------------
__global__ void __launch_bounds__(256) k_gemm0(
    const float* __restrict__ Wc, const float* __restrict__ emb,
    const int* __restrict__ xz)
{
    __shared__ float4 Ws4[HH * 8];
    int t = threadIdx.x;
    if (t < HH * 8) Ws4[t] = ((const float4*)Wc)[t];
    __syncthreads();

    int n = blockIdx.x * 256 + t;
    float xin[HH];
    const float4* ep = (const float4*)(emb + (size_t)xz[n] * HH);
#pragma unroll
    for (int q = 0; q < 8; q++) {
        float4 v = ep[q];
        xin[4 * q + 0] = v.x; xin[4 * q + 1] = v.y;
        xin[4 * q + 2] = v.z; xin[4 * q + 3] = v.w;
    }

    float4 out[8];
#pragma unroll
    for (int q = 0; q < 8; q++) out[q] = make_float4(0.f, 0.f, 0.f, 0.f);
#pragma unroll
    for (int k = 0; k < HH; k++) {
        float xk = xin[k];
#pragma unroll
        for (int q = 0; q < 8; q++) {
            float4 w4 = Ws4[k * 8 + q];
            out[q].x = fmaf(xk, w4.x, out[q].x);
            out[q].y = fmaf(xk, w4.y, out[q].y);
            out[q].z = fmaf(xk, w4.z, out[q].z);
            out[q].w = fmaf(xk, w4.w, out[q].w);
        }
    }

    float dn = g_dinv[n];
    float4* hp = (float4*)(g_ha + (size_t)n * HH);
#pragma unroll
    for (int q = 0; q < 8; q++) {
        float4 hv;
        hv.x = out[q].x * dn; hv.y = out[q].y * dn;
        hv.z = out[q].z * dn; hv.w = out[q].w * dn;
        hp[q] = hv;
    }
}

// ---------------- fused: gather_l + BN_l + ReLU + GEMM_{l+1}, warp/node -----
// S = sum_csr h'[src] + h'[n];  x = relu((S*dinv + bc)*sc + sh)
// hout[n] = (x @ W_{l+1}) * dinv[n]
__global__ void __launch_bounds__(256) k_fused(
    int bnl, int dir,
    const float* __restrict__ Wc, const float* __restrict__ bcp,
    const float* __restrict__ gamma, const float* __restrict__ beta,
    const float* __restrict__ rmean, const float* __restrict__ rvar)
{
    __shared__ float Ws[HH * HH];
    __shared__ float sA[HH];   // ssc (BN scale)
    __shared__ float sB[HH];   // sbc*ssc + ssh (fused shift)
    int t = threadIdx.x;
    for (int i = t; i < HH * HH; i += 256) Ws[i] = Wc[(bnl + 1) * HH * HH + i];
    if (t < HH) {
        float sc = gamma[bnl * HH + t] * rsqrtf(rvar[bnl * HH + t] + EPSF);
        float sh = beta[bnl * HH + t] - rmean[bnl * HH + t] * sc;
        sA[t] = sc;
        sB[t] = fmaf(bcp[bnl * HH + t], sc, sh);
    }
    __syncthreads();

    int n = (blockIdx.x * 256 + t) >> 5;   // one warp per node
    int lane = t & 31;
    int g = lane >> 3, p = lane & 7;

    const float* hin = dir ? g_hb : g_ha;
    float*       hout = dir ? g_ha : g_hb;

    int beg = g_rowstart[n];
    int end = g_rowstart[n + 1];

    float4 acc = make_float4(0.f, 0.f, 0.f, 0.f);
    for (int r = beg + g; r < end; r += 4) {
        int s = __ldcs(&g_csrsrc[r]);
        float4 hv = __ldg((const float4*)(hin + (size_t)s * HH) + p);
        acc.x += hv.x; acc.y += hv.y; acc.z += hv.z; acc.w += hv.w;
    }
#pragma unroll
    for (int m = 8; m <= 16; m <<= 1) {
        acc.x += __shfl_xor_sync(0xffffffffu, acc.x, m);
        acc.y += __shfl_xor_sync(0xffffffffu, acc.y, m);
        acc.z += __shfl_xor_sync(0xffffffffu, acc.z, m);
        acc.w += __shfl_xor_sync(0xffffffffu, acc.w, m);
    }
    float4 selfv = __ldg((const float4*)(hin + (size_t)n * HH) + p);
    acc.x += selfv.x; acc.y += selfv.y; acc.z += selfv.z; acc.w += selfv.w;

    float dn = g_dinv[n];
    float xr[4];
    xr[0] = fmaxf(fmaf(acc.x, dn * sA[4 * p + 0], sB[4 * p + 0]), 0.f);
    xr[1] = fmaxf(fmaf(acc.y, dn * sA[4 * p + 1], sB[4 * p + 1]), 0.f);
    xr[2] = fmaxf(fmaf(acc.z, dn * sA[4 * p + 2], sB[4 * p + 2]), 0.f);
    xr[3] = fmaxf(fmaf(acc.w, dn * sA[4 * p + 3], sB[4 * p + 3]), 0.f);

    float out = 0.f;
#pragma unroll
    for (int k = 0; k < HH; k++) {
        float xk = __shfl_sync(0xffffffffu, xr[k & 3], k >> 2);
        out = fmaf(xk, Ws[k * HH + lane], out);
    }
    hout[(size_t)n * HH + lane] = out * dn;
}

// ---------------- final layer: gather + BN2 + ReLU -> g_x -------------------
__global__ void __launch_bounds__(256) k_final(
    int dir,
    const float* __restrict__ bcp,
    const float* __restrict__ gamma, const float* __restrict__ beta,
    const float* __restrict__ rmean, const float* __restrict__ rvar)
{
    __shared__ float sA[HH], sB[HH];
    int t = threadIdx.x;
    if (t < HH) {
        float sc = gamma[2 * HH + t] * rsqrtf(rvar[2 * HH + t] + EPSF);
        float sh = beta[2 * HH + t] - rmean[2 * HH + t] * sc;
        sA[t] = sc;
        sB[t] = fmaf(bcp[2 * HH + t], sc, sh);
    }
    __syncthreads();

    int n = (blockIdx.x * 256 + t) >> 5;
    int lane = t & 31;
    int g = lane >> 3, p = lane & 7;

    const float* hin = dir ? g_hb : g_ha;

    int beg = g_rowstart[n];
    int end = g_rowstart[n + 1];

    float4 acc = make_float4(0.f, 0.f, 0.f, 0.f);
    for (int r = beg + g; r < end; r += 4) {
        int s = __ldcs(&g_csrsrc[r]);
        float4 hv = __ldg((const float4*)(hin + (size_t)s * HH) + p);
        acc.x += hv.x; acc.y += hv.y; acc.z += hv.z; acc.w += hv.w;
    }
#pragma unroll
    for (int m = 8; m <= 16; m <<= 1) {
        acc.x += __shfl_xor_sync(0xffffffffu, acc.x, m);
        acc.y += __shfl_xor_sync(0xffffffffu, acc.y, m);
        acc.z += __shfl_xor_sync(0xffffffffu, acc.z, m);
        acc.w += __shfl_xor_sync(0xffffffffu, acc.w, m);
    }
    float4 selfv = __ldg((const float4*)(hin + (size_t)n * HH) + p);
    acc.x += selfv.x; acc.y += selfv.y; acc.z += selfv.z; acc.w += selfv.w;

    float dn = g_dinv[n];
    float4 xv;
    xv.x = fmaxf(fmaf(acc.x, dn * sA[4 * p + 0], sB[4 * p + 0]), 0.f);
    xv.y = fmaxf(fmaf(acc.y, dn * sA[4 * p + 1], sB[4 * p + 1]), 0.f);
    xv.z = fmaxf(fmaf(acc.z, dn * sA[4 * p + 2], sB[4 * p + 2]), 0.f);
    xv.w = fmaxf(fmaf(acc.w, dn * sA[4 * p + 3], sB[4 * p + 3]), 0.f);

    if (g == 0) ((float4*)(g_x + (size_t)n * HH))[p] = xv;
}

// ---------------- SortPool (x already BN+ReLU'd, nonneg) --------------------
__global__ void __launch_bounds__(256) k_sortpool() {
    __shared__ unsigned long long keys[CAP];
    __shared__ int ssel[KK];
    int b = blockIdx.x, t = threadIdx.x;

    int start = g_start2[b];
    int cnt = g_start2[b + 1] - start;
    int cc = min(cnt, CAP);

    for (int r = t; r < CAP; r += 256) {
        unsigned long long key = 0xFFFFFFFFFFFFFFFFull;
        if (r < cc) {
            float v = g_x[(size_t)(start + r) * HH + 31];  // nonneg
            unsigned u = (v == 0.0f) ? 0u : __float_as_uint(v);
            key = ((unsigned long long)(~u) << 32) | (unsigned)r;
        }
        keys[r] = key;
    }
    __syncthreads();

    for (int k = 2; k <= CAP; k <<= 1) {
        for (int j = k >> 1; j > 0; j >>= 1) {
            for (int base = 0; base < CAP; base += 256) {
                int i = base + t;
                int ixj = i ^ j;
                if (ixj > i) {
                    unsigned long long a = keys[i], c = keys[ixj];
                    bool up = ((i & k) == 0);
                    bool sw = up ? (a > c) : (a < c);
                    if (sw) { keys[i] = c; keys[ixj] = a; }
                }
            }
            __syncthreads();
        }
    }

    int nval = min(cc, KK);
    if (t < KK) ssel[t] = (t < nval) ? (int)(unsigned)(keys[t] & 0xFFFFFFFFu) : -1;
    __syncthreads();

    for (int idx = t; idx < KK * HH; idx += 256) {
        int k = idx >> 5, j = idx & 31;
        float v = 0.f;
        int r = ssel[k];
        if (r >= 0) v = g_x[(size_t)(start + r) * HH + j];
        g_pooled[(size_t)b * (KK * HH) + idx] = v;
    }
}

// ---------------- MLP head: warp per graph ----------------------------------
__global__ void __launch_bounds__(256) k_mlp(
    const float* __restrict__ W1, const float* __restrict__ b1,
    const float* __restrict__ W2, const float* __restrict__ b2,
    const float* __restrict__ W3, const float* __restrict__ b3,
    float* __restrict__ out)
{
    int gwarp = (blockIdx.x * 256 + threadIdx.x) >> 5;
    int lane = threadIdx.x & 31;
    if (gwarp >= BB) return;

    const float* pr = g_pooled + (size_t)gwarp * (KK * HH);
    float acc = b1[lane];
    for (int p0 = 0; p0 < KK * HH; p0 += 32) {
        float xv = pr[p0 + lane];
#pragma unroll
        for (int jj = 0; jj < 32; jj++) {
            float xs = __shfl_sync(0xffffffffu, xv, jj);
            acc = fmaf(xs, W1[(p0 + jj) * 32 + lane], acc);
        }
    }
    float h1 = fmaxf(acc, 0.f);

    float pm[16];
#pragma unroll
    for (int m = 0; m < 16; m++) pm[m] = h1 * W2[lane * 16 + m];
#pragma unroll
    for (int off = 16; off; off >>= 1) {
#pragma unroll
        for (int m = 0; m < 16; m++) pm[m] += __shfl_xor_sync(0xffffffffu, pm[m], off);
    }
    float o = b3[0];
#pragma unroll
    for (int m = 0; m < 16; m++) o = fmaf(fmaxf(pm[m] + b2[m], 0.f), W3[m], o);
    if (lane == 0) out[gwarp] = o;
}

// ---------------- launch -----------------------------------------------------
extern "C" void kernel_launch(void* const* d_in, const int* in_sizes, int n_in,
                              void* d_out, int out_size) {
    const int*   xz    = (const int*)d_in[0];
    const int*   ei    = (const int*)d_in[1];
    const int*   batch = (const int*)d_in[2];
    const float* emb   = (const float*)d_in[3];
    const float* Wc    = (const float*)d_in[4];
    const float* bc    = (const float*)d_in[5];
    const float* gamma = (const float*)d_in[6];
    const float* beta  = (const float*)d_in[7];
    const float* rmean = (const float*)d_in[8];
    const float* rvar  = (const float*)d_in[9];
    const float* W1    = (const float*)d_in[10];
    const float* b1    = (const float*)d_in[11];
    const float* W2    = (const float*)d_in[12];
    const float* b2    = (const float*)d_in[13];
    const float* W3    = (const float*)d_in[14];
    const float* b3    = (const float*)d_in[15];
    float* out = (float*)d_out;

    const int* src = ei;
    const int* dst = ei + EE;

    k_zero  <<<NBLK, 256>>>();                    // 1
    k_degb  <<<EE / 256, 256>>>(dst, batch);      // 2
    k_scanlb<<<NBLK, 256>>>();                    // 3
    k_fill  <<<EE / 256, 256>>>(src, dst);        // 4
    k_gemm0 <<<NBLK, 256>>>(Wc, emb, xz);         // 5
    // fused layers: gather + BN + ReLU + next GEMM (warp per node)
    k_fused <<<NN / 8, 256>>>(0, 0, Wc, bc, gamma, beta, rmean, rvar);  // 6 (profiled)
    k_fused <<<NN / 8, 256>>>(1, 1, Wc, bc, gamma, beta, rmean, rvar);  // 7
    k_final <<<NN / 8, 256>>>(0, bc, gamma, beta, rmean, rvar);         // 8
    k_sortpool<<<BB, 256>>>();                                          // 9
    k_mlp   <<<BB / 8, 256>>>(W1, b1, W2, b2, W3, b3, out);             // 10
}

// round 4
// speedup vs baseline: 1.2669x; 1.2669x over previous
#include <cuda_runtime.h>

#define NN 524288
#define EE 4194304
#define BB 4096
#define HH 32
#define KK 30
#define CAP 512
#define EPSF 1e-5f
#define NBLK 2048          // NN/256

// ---------------- scratch (device globals; no allocation allowed) ----------
__device__ int   g_deg[NN];
__device__ float g_dinv[NN];
__device__ float g_ha[(size_t)NN * HH];   // h' ping
__device__ float g_hb[(size_t)NN * HH];   // h' pong
__device__ float g_agg[(size_t)NN * HH];  // gathered sums (pre-BN)
__device__ float g_x[(size_t)NN * HH];    // final activations
__device__ int   g_rowstart[NN + 1];
__device__ int   g_cursor[NN];
__device__ int   g_csrsrc[EE];
__device__ int   g_bsum[NBLK];
__device__ int   g_start2[BB + 1];
__device__ float g_pooled[(size_t)BB * KK * HH];

__device__ __forceinline__ float4 add4(float4 a, float4 b) {
    return make_float4(a.x + b.x, a.y + b.y, a.z + b.z, a.w + b.w);
}

// ---------------- setup -----------------------------------------------------
__global__ void k_zero() {
    int i = blockIdx.x * 256 + threadIdx.x;
    g_deg[i] = 0;
}

// in-degree histogram + graph-boundary detection (batch is sorted)
__global__ void k_degb(const int* __restrict__ dst, const int* __restrict__ batch) {
    int i = blockIdx.x * 256 + threadIdx.x;   // grid covers EE
    atomicAdd(&g_deg[dst[i]], 1);
    if (i < NN) {
        int b1 = batch[i];
        int b0 = (i > 0) ? batch[i - 1] : -1;
        for (int b = b0 + 1; b <= b1; b++) g_start2[b] = i;
        if (i == NN - 1)
            for (int b = b1 + 1; b <= BB; b++) g_start2[b] = NN;
    }
}

// ---------------- 3-kernel exclusive scan of g_deg --------------------------
__global__ void k_scan1() {
    __shared__ int s[256];
    int t = threadIdx.x;
    s[t] = g_deg[blockIdx.x * 256 + t];
    __syncthreads();
    for (int off = 128; off; off >>= 1) {
        if (t < off) s[t] += s[t + off];
        __syncthreads();
    }
    if (t == 0) g_bsum[blockIdx.x] = s[0];
}

__global__ void k_scan2() {   // exclusive scan of g_bsum[2048] (1 block)
    __shared__ int s[1024];
    int t = threadIdx.x;
    int a = g_bsum[2 * t], b = g_bsum[2 * t + 1];
    int sum = a + b;
    s[t] = sum;
    __syncthreads();
    for (int off = 1; off < 1024; off <<= 1) {
        int v = (t >= off) ? s[t - off] : 0;
        __syncthreads();
        s[t] += v;
        __syncthreads();
    }
    int excl = s[t] - sum;
    g_bsum[2 * t] = excl;
    g_bsum[2 * t + 1] = excl + a;
}

__global__ void k_scan3() {   // per-element scan + block offset; also dinv
    __shared__ int s[256];
    int t = threadIdx.x;
    int i = blockIdx.x * 256 + t;
    int d = g_deg[i];
    g_dinv[i] = rsqrtf((float)d + 1.0f);
    s[t] = d;
    __syncthreads();
    for (int off = 1; off < 256; off <<= 1) {
        int v = (t >= off) ? s[t - off] : 0;
        __syncthreads();
        s[t] += v;
        __syncthreads();
    }
    int excl = s[t] - d + g_bsum[blockIdx.x];
    g_rowstart[i] = excl;
    g_cursor[i] = excl;
    if (i == NN - 1) g_rowstart[NN] = EE;
}

// ---------------- CSR fill: src index only ----------------------------------
__global__ void k_fill(const int* __restrict__ src, const int* __restrict__ dst) {
    int e = blockIdx.x * 256 + threadIdx.x;   // grid covers EE
    int s = src[e], d = dst[e];
    int pos = atomicAdd(&g_cursor[d], 1);
    g_csrsrc[pos] = s;
}

// ---------------- layer 0: h0' = (emb[xz] @ W0) * dinv ----------------------
__global__ void __launch_bounds__(256) k_gemm0(
    const float* __restrict__ Wc, const float* __restrict__ emb,
    const int* __restrict__ xz)
{
    __shared__ float4 Ws4[HH * 8];
    int t = threadIdx.x;
    if (t < HH * 8) Ws4[t] = ((const float4*)Wc)[t];
    __syncthreads();

    int n = blockIdx.x * 256 + t;
    float xin[HH];
    const float4* ep = (const float4*)(emb + (size_t)xz[n] * HH);
#pragma unroll
    for (int q = 0; q < 8; q++) {
        float4 v = ep[q];
        xin[4 * q + 0] = v.x; xin[4 * q + 1] = v.y;
        xin[4 * q + 2] = v.z; xin[4 * q + 3] = v.w;
    }

    float4 out[8];
#pragma unroll
    for (int q = 0; q < 8; q++) out[q] = make_float4(0.f, 0.f, 0.f, 0.f);
#pragma unroll
    for (int k = 0; k < HH; k++) {
        float xk = xin[k];
#pragma unroll
        for (int q = 0; q < 8; q++) {
            float4 w4 = Ws4[k * 8 + q];
            out[q].x = fmaf(xk, w4.x, out[q].x);
            out[q].y = fmaf(xk, w4.y, out[q].y);
            out[q].z = fmaf(xk, w4.z, out[q].z);
            out[q].w = fmaf(xk, w4.w, out[q].w);
        }
    }

    float dn = g_dinv[n];
    float4* hp = (float4*)(g_ha + (size_t)n * HH);
#pragma unroll
    for (int q = 0; q < 8; q++) {
        float4 hv;
        hv.x = out[q].x * dn; hv.y = out[q].y * dn;
        hv.z = out[q].z * dn; hv.w = out[q].w * dn;
        hp[q] = hv;
    }
}

// ---------------- batched pull gather, 8 threads/node -----------------------
// agg[n] = dinv[n] * (sum_csr h'[src] + h'[n])          (bias folded later)
// final=1: g_x[n] = relu(agg*sA + sB) with layer-2 BN consts (bias folded)
__global__ void __launch_bounds__(256) k_gather(
    int dir, int final_,
    const float* __restrict__ bcp,
    const float* __restrict__ gamma, const float* __restrict__ beta,
    const float* __restrict__ rmean, const float* __restrict__ rvar)
{
    __shared__ float sA[HH], sB[HH];
    int t = threadIdx.x;
    if (final_ && t < HH) {
        float sc = gamma[2 * HH + t] * rsqrtf(rvar[2 * HH + t] + EPSF);
        float sh = beta[2 * HH + t] - rmean[2 * HH + t] * sc;
        sA[t] = sc;
        sB[t] = fmaf(bcp[2 * HH + t], sc, sh);
    }
    if (final_) __syncthreads();

    int tid = blockIdx.x * 256 + t;   // grid covers NN*8
    int n = tid >> 3;
    int p = tid & 7;

    const float* hin = dir ? g_hb : g_ha;
    const float4* hp = (const float4*)hin;

    int beg = __ldg(&g_rowstart[n]);
    int end = __ldg(&g_rowstart[n + 1]);

    // self contribution
    float4 acc = __ldg(hp + (size_t)n * 8 + p);

    int r = beg;
    // batch of 8: prefetch indices, then 8 independent gathers (MLP=8)
    while (r + 8 <= end) {
        int idx[8];
#pragma unroll
        for (int j = 0; j < 8; j++) idx[j] = __ldcs(&g_csrsrc[r + j]);
        float4 hv[8];
#pragma unroll
        for (int j = 0; j < 8; j++) hv[j] = __ldg(hp + (size_t)idx[j] * 8 + p);
        float4 s01 = add4(hv[0], hv[1]);
        float4 s23 = add4(hv[2], hv[3]);
        float4 s45 = add4(hv[4], hv[5]);
        float4 s67 = add4(hv[6], hv[7]);
        acc = add4(acc, add4(add4(s01, s23), add4(s45, s67)));
        r += 8;
    }
    if (r + 4 <= end) {
        int idx[4];
#pragma unroll
        for (int j = 0; j < 4; j++) idx[j] = __ldcs(&g_csrsrc[r + j]);
        float4 hv[4];
#pragma unroll
        for (int j = 0; j < 4; j++) hv[j] = __ldg(hp + (size_t)idx[j] * 8 + p);
        acc = add4(acc, add4(add4(hv[0], hv[1]), add4(hv[2], hv[3])));
        r += 4;
    }
    for (; r < end; r++) {
        int s = __ldcs(&g_csrsrc[r]);
        acc = add4(acc, __ldg(hp + (size_t)s * 8 + p));
    }

    float dn = g_dinv[n];
    acc.x *= dn; acc.y *= dn; acc.z *= dn; acc.w *= dn;

    if (!final_) {
        __stcs((float4*)(g_agg + (size_t)n * HH) + p, acc);
    } else {
        float4 xv;
        xv.x = fmaxf(fmaf(acc.x, sA[4 * p + 0], sB[4 * p + 0]), 0.f);
        xv.y = fmaxf(fmaf(acc.y, sA[4 * p + 1], sB[4 * p + 1]), 0.f);
        xv.z = fmaxf(fmaf(acc.z, sA[4 * p + 2], sB[4 * p + 2]), 0.f);
        xv.w = fmaxf(fmaf(acc.w, sA[4 * p + 3], sB[4 * p + 3]), 0.f);
        ((float4*)(g_x + (size_t)n * HH))[p] = xv;
    }
}

// ---------------- mid layers: BN_l + ReLU + GEMM_{l+1}, thread/node ---------
// h' = (relu(agg*sA + sB) @ W_{l+1}) * dinv
__global__ void __launch_bounds__(256) k_gemm(
    int bnl, int dir,
    const float* __restrict__ Wc, const float* __restrict__ bcp,
    const float* __restrict__ gamma, const float* __restrict__ beta,
    const float* __restrict__ rmean, const float* __restrict__ rvar)
{
    __shared__ float4 Ws4[HH * 8];
    __shared__ float sA[HH], sB[HH];
    int t = threadIdx.x;
    if (t < HH * 8) Ws4[t] = ((const float4*)(Wc + (bnl + 1) * HH * HH))[t];
    if (t < HH) {
        float sc = gamma[bnl * HH + t] * rsqrtf(rvar[bnl * HH + t] + EPSF);
        float sh = beta[bnl * HH + t] - rmean[bnl * HH + t] * sc;
        sA[t] = sc;
        sB[t] = fmaf(bcp[bnl * HH + t], sc, sh);
    }
    __syncthreads();

    int n = blockIdx.x * 256 + t;
    float xin[HH];
    const float4* ap = (const float4*)(g_agg + (size_t)n * HH);
#pragma unroll
    for (int q = 0; q < 8; q++) {
        float4 v = __ldcs(ap + q);
        xin[4 * q + 0] = fmaxf(fmaf(v.x, sA[4 * q + 0], sB[4 * q + 0]), 0.f);
        xin[4 * q + 1] = fmaxf(fmaf(v.y, sA[4 * q + 1], sB[4 * q + 1]), 0.f);
        xin[4 * q + 2] = fmaxf(fmaf(v.z, sA[4 * q + 2], sB[4 * q + 2]), 0.f);
        xin[4 * q + 3] = fmaxf(fmaf(v.w, sA[4 * q + 3], sB[4 * q + 3]), 0.f);
    }

    float4 out[8];
#pragma unroll
    for (int q = 0; q < 8; q++) out[q] = make_float4(0.f, 0.f, 0.f, 0.f);
#pragma unroll
    for (int k = 0; k < HH; k++) {
        float xk = xin[k];
#pragma unroll
        for (int q = 0; q < 8; q++) {
            float4 w4 = Ws4[k * 8 + q];
            out[q].x = fmaf(xk, w4.x, out[q].x);
            out[q].y = fmaf(xk, w4.y, out[q].y);
            out[q].z = fmaf(xk, w4.z, out[q].z);
            out[q].w = fmaf(xk, w4.w, out[q].w);
        }
    }

    float dn = g_dinv[n];
    float* hout = dir ? g_ha : g_hb;   // dir: which buffer is the OLD input
    float4* hp = (float4*)(hout + (size_t)n * HH);
#pragma unroll
    for (int q = 0; q < 8; q++) {
        float4 hv;
        hv.x = out[q].x * dn; hv.y = out[q].y * dn;
        hv.z = out[q].z * dn; hv.w = out[q].w * dn;
        hp[q] = hv;
    }
}

// ---------------- SortPool (x already BN+ReLU'd, nonneg) --------------------
__global__ void __launch_bounds__(256) k_sortpool() {
    __shared__ unsigned long long keys[CAP];
    __shared__ int ssel[KK];
    int b = blockIdx.x, t = threadIdx.x;

    int start = g_start2[b];
    int cnt = g_start2[b + 1] - start;
    int cc = min(cnt, CAP);

    for (int r = t; r < CAP; r += 256) {
        unsigned long long key = 0xFFFFFFFFFFFFFFFFull;
        if (r < cc) {
            float v = g_x[(size_t)(start + r) * HH + 31];  // nonneg
            unsigned u = (v == 0.0f) ? 0u : __float_as_uint(v);
            key = ((unsigned long long)(~u) << 32) | (unsigned)r;
        }
        keys[r] = key;
    }
    __syncthreads();

    for (int k = 2; k <= CAP; k <<= 1) {
        for (int j = k >> 1; j > 0; j >>= 1) {
            for (int base = 0; base < CAP; base += 256) {
                int i = base + t;
                int ixj = i ^ j;
                if (ixj > i) {
                    unsigned long long a = keys[i], c = keys[ixj];
                    bool up = ((i & k) == 0);
                    bool sw = up ? (a > c) : (a < c);
                    if (sw) { keys[i] = c; keys[ixj] = a; }
                }
            }
            __syncthreads();
        }
    }

    int nval = min(cc, KK);
    if (t < KK) ssel[t] = (t < nval) ? (int)(unsigned)(keys[t] & 0xFFFFFFFFu) : -1;
    __syncthreads();

    for (int idx = t; idx < KK * HH; idx += 256) {
        int k = idx >> 5, j = idx & 31;
        float v = 0.f;
        int r = ssel[k];
        if (r >= 0) v = g_x[(size_t)(start + r) * HH + j];
        g_pooled[(size_t)b * (KK * HH) + idx] = v;
    }
}

// ---------------- MLP head: warp per graph ----------------------------------
__global__ void __launch_bounds__(256) k_mlp(
    const float* __restrict__ W1, const float* __restrict__ b1,
    const float* __restrict__ W2, const float* __restrict__ b2,
    const float* __restrict__ W3, const float* __restrict__ b3,
    float* __restrict__ out)
{
    int gwarp = (blockIdx.x * 256 + threadIdx.x) >> 5;
    int lane = threadIdx.x & 31;
    if (gwarp >= BB) return;

    const float* pr = g_pooled + (size_t)gwarp * (KK * HH);
    float acc = b1[lane];
    for (int p0 = 0; p0 < KK * HH; p0 += 32) {
        float xv = pr[p0 + lane];
#pragma unroll
        for (int jj = 0; jj < 32; jj++) {
            float xs = __shfl_sync(0xffffffffu, xv, jj);
            acc = fmaf(xs, W1[(p0 + jj) * 32 + lane], acc);
        }
    }
    float h1 = fmaxf(acc, 0.f);

    float pm[16];
#pragma unroll
    for (int m = 0; m < 16; m++) pm[m] = h1 * W2[lane * 16 + m];
#pragma unroll
    for (int off = 16; off; off >>= 1) {
#pragma unroll
        for (int m = 0; m < 16; m++) pm[m] += __shfl_xor_sync(0xffffffffu, pm[m], off);
    }
    float o = b3[0];
#pragma unroll
    for (int m = 0; m < 16; m++) o = fmaf(fmaxf(pm[m] + b2[m], 0.f), W3[m], o);
    if (lane == 0) out[gwarp] = o;
}

// ---------------- launch -----------------------------------------------------
extern "C" void kernel_launch(void* const* d_in, const int* in_sizes, int n_in,
                              void* d_out, int out_size) {
    const int*   xz    = (const int*)d_in[0];
    const int*   ei    = (const int*)d_in[1];
    const int*   batch = (const int*)d_in[2];
    const float* emb   = (const float*)d_in[3];
    const float* Wc    = (const float*)d_in[4];
    const float* bc    = (const float*)d_in[5];
    const float* gamma = (const float*)d_in[6];
    const float* beta  = (const float*)d_in[7];
    const float* rmean = (const float*)d_in[8];
    const float* rvar  = (const float*)d_in[9];
    const float* W1    = (const float*)d_in[10];
    const float* b1    = (const float*)d_in[11];
    const float* W2    = (const float*)d_in[12];
    const float* b2    = (const float*)d_in[13];
    const float* W3    = (const float*)d_in[14];
    const float* b3    = (const float*)d_in[15];
    float* out = (float*)d_out;

    const int* src = ei;
    const int* dst = ei + EE;

    k_zero <<<NBLK, 256>>>();
    k_degb <<<EE / 256, 256>>>(dst, batch);
    k_scan1<<<NBLK, 256>>>();
    k_scan2<<<1, 1024>>>();
    k_scan3<<<NBLK, 256>>>();
    k_fill <<<EE / 256, 256>>>(src, dst);
    k_gemm0<<<NBLK, 256>>>(Wc, emb, xz);
    // layer 0 gather -> agg ; BN0+GEMM1 -> h'1
    k_gather<<<(NN * 8) / 256, 256>>>(0, 0, bc, gamma, beta, rmean, rvar);
    k_gemm  <<<NBLK, 256>>>(0, 0, Wc, bc, gamma, beta, rmean, rvar);
    // layer 1 gather -> agg ; BN1+GEMM2 -> h'2
    k_gather<<<(NN * 8) / 256, 256>>>(1, 0, bc, gamma, beta, rmean, rvar);
    k_gemm  <<<NBLK, 256>>>(1, 1, Wc, bc, gamma, beta, rmean, rvar);
    // layer 2 gather + BN2 + ReLU -> g_x
    k_gather<<<(NN * 8) / 256, 256>>>(0, 1, bc, gamma, beta, rmean, rvar);
    k_sortpool<<<BB, 256>>>();
    k_mlp  <<<BB / 8, 256>>>(W1, b1, W2, b2, W3, b3, out);
}

// round 5
// speedup vs baseline: 1.3338x; 1.0528x over previous
#include <cuda_runtime.h>

#define NN 524288
#define EE 4194304
#define BB 4096
#define HH 32
#define KK 30
#define CAP 512
#define EPSF 1e-5f
#define NBLK 2048          // NN/256

// ---------------- scratch (device globals; no allocation allowed) ----------
__device__ int   g_deg[NN];
__device__ float g_dinv[NN];
__device__ float g_ha[(size_t)NN * HH];   // h' ping
__device__ float g_hb[(size_t)NN * HH];   // h' pong
__device__ float g_x[(size_t)NN * HH];    // final activations
__device__ int   g_rowstart[NN + 1];
__device__ int   g_cursor[NN];
__device__ int   g_csrsrc[EE];
__device__ int   g_bsum[NBLK];
__device__ int   g_start2[BB + 1];
__device__ float g_pooled[(size_t)BB * KK * HH];

__device__ __forceinline__ float4 add4(float4 a, float4 b) {
    return make_float4(a.x + b.x, a.y + b.y, a.z + b.z, a.w + b.w);
}
__device__ __forceinline__ unsigned long long pk2(float x, float y) {
    unsigned long long r;
    asm("mov.b64 %0, {%1,%2};" : "=l"(r) : "f"(x), "f"(y));
    return r;
}
__device__ __forceinline__ void fma2(unsigned long long& d, unsigned long long a,
                                     unsigned long long b) {
    asm("fma.rn.f32x2 %0, %1, %2, %0;" : "+l"(d) : "l"(a), "l"(b));
}
__device__ __forceinline__ unsigned long long mul2(unsigned long long a,
                                                   unsigned long long b) {
    unsigned long long r;
    asm("mul.rn.f32x2 %0, %1, %2;" : "=l"(r) : "l"(a), "l"(b));
    return r;
}

// ---------------- setup -----------------------------------------------------
__global__ void k_zero() {
    int i = blockIdx.x * 256 + threadIdx.x;
    g_deg[i] = 0;
}

// in-degree histogram + graph-boundary detection (batch is sorted)
__global__ void k_degb(const int* __restrict__ dst, const int* __restrict__ batch) {
    int i = blockIdx.x * 256 + threadIdx.x;   // grid covers EE
    atomicAdd(&g_deg[dst[i]], 1);
    if (i < NN) {
        int b1 = batch[i];
        int b0 = (i > 0) ? batch[i - 1] : -1;
        for (int b = b0 + 1; b <= b1; b++) g_start2[b] = i;
        if (i == NN - 1)
            for (int b = b1 + 1; b <= BB; b++) g_start2[b] = NN;
    }
}

// scanA: block sums of deg + dinv
__global__ void k_scanA() {
    __shared__ int s[256];
    int t = threadIdx.x;
    int i = blockIdx.x * 256 + t;
    int d = g_deg[i];
    g_dinv[i] = rsqrtf((float)d + 1.0f);
    s[t] = d;
    __syncthreads();
    for (int off = 128; off; off >>= 1) {
        if (t < off) s[t] += s[t + off];
        __syncthreads();
    }
    if (t == 0) g_bsum[blockIdx.x] = s[0];
}

// scanB: each block sums its bsum prefix directly, then local scan
__global__ void __launch_bounds__(256) k_scanB() {
    __shared__ int red[256];
    __shared__ int s[256];
    int b = blockIdx.x, t = threadIdx.x;
    int part = 0;
    for (int j = t; j < b; j += 256) part += g_bsum[j];
    red[t] = part;
    __syncthreads();
    for (int off = 128; off; off >>= 1) {
        if (t < off) red[t] += red[t + off];
        __syncthreads();
    }
    int base = red[0];
    int i = b * 256 + t;
    int d = g_deg[i];
    s[t] = d;
    __syncthreads();
    for (int off = 1; off < 256; off <<= 1) {
        int v = (t >= off) ? s[t - off] : 0;
        __syncthreads();
        s[t] += v;
        __syncthreads();
    }
    int excl = base + s[t] - d;
    g_rowstart[i] = excl;
    g_cursor[i] = excl;
    if (i == NN - 1) g_rowstart[NN] = EE;
}

// ---------------- CSR fill: src index only ----------------------------------
__global__ void k_fill(const int* __restrict__ src, const int* __restrict__ dst) {
    int e = blockIdx.x * 256 + threadIdx.x;   // grid covers EE
    int s = src[e], d = dst[e];
    int pos = atomicAdd(&g_cursor[d], 1);
    g_csrsrc[pos] = s;
}

// ---------------- layer 0: h0' = (emb[xz] @ W0) * dinv  (f32x2 FMA) ---------
__global__ void __launch_bounds__(256) k_gemm0(
    const float* __restrict__ Wc, const float* __restrict__ emb,
    const int* __restrict__ xz)
{
    __shared__ ulonglong2 Ws2[HH * 8];
    int t = threadIdx.x;
    if (t < HH * 8) Ws2[t] = ((const ulonglong2*)Wc)[t];
    __syncthreads();

    int n = blockIdx.x * 256 + t;
    float xin[HH];
    const float4* ep = (const float4*)(emb + (size_t)xz[n] * HH);
#pragma unroll
    for (int q = 0; q < 8; q++) {
        float4 v = __ldg(ep + q);
        xin[4 * q + 0] = v.x; xin[4 * q + 1] = v.y;
        xin[4 * q + 2] = v.z; xin[4 * q + 3] = v.w;
    }

    unsigned long long o2[16];
#pragma unroll
    for (int q = 0; q < 16; q++) o2[q] = 0ULL;
#pragma unroll
    for (int k = 0; k < HH; k++) {
        unsigned long long xkk = pk2(xin[k], xin[k]);
#pragma unroll
        for (int q = 0; q < 8; q++) {
            ulonglong2 w = Ws2[k * 8 + q];
            fma2(o2[2 * q], xkk, w.x);
            fma2(o2[2 * q + 1], xkk, w.y);
        }
    }

    float dn = rsqrtf((float)g_deg[n] + 1.0f);
    unsigned long long dn2 = pk2(dn, dn);
    ulonglong2* hp = (ulonglong2*)(g_ha + (size_t)n * HH);
#pragma unroll
    for (int q = 0; q < 8; q++)
        hp[q] = make_ulonglong2(mul2(o2[2 * q], dn2), mul2(o2[2 * q + 1], dn2));
}

// ---------------- fused gather + BN + ReLU + next GEMM ----------------------
// block = 32 nodes x 8 threads.  bnl=0: ha->hb, bnl=1: hb->ha
__global__ void __launch_bounds__(256) k_gbg(
    int bnl,
    const float* __restrict__ Wc, const float* __restrict__ bcp,
    const float* __restrict__ gamma, const float* __restrict__ beta,
    const float* __restrict__ rmean, const float* __restrict__ rvar)
{
    __shared__ ulonglong2 Ws2[HH * 8];
    __shared__ float sA[HH], sB[HH];
    __shared__ float xs[32 * 40];   // 32 nodes, row stride 40 floats (bank-safe)
    int t = threadIdx.x;
    if (t < HH * 8) Ws2[t] = ((const ulonglong2*)(Wc + (bnl + 1) * HH * HH))[t];
    if (t < HH) {
        float sc = gamma[bnl * HH + t] * rsqrtf(rvar[bnl * HH + t] + EPSF);
        float sh = beta[bnl * HH + t] - rmean[bnl * HH + t] * sc;
        sA[t] = sc;
        sB[t] = fmaf(bcp[bnl * HH + t], sc, sh);
    }
    __syncthreads();

    int tid = blockIdx.x * 256 + t;   // grid covers NN*8
    int n = tid >> 3;
    int p = tid & 7;
    int nl = t >> 3;

    const float* hin = bnl ? g_hb : g_ha;
    float*       hout = bnl ? g_ha : g_hb;
    const float4* hp = (const float4*)hin;

    int beg = __ldg(&g_rowstart[n]);
    int end = __ldg(&g_rowstart[n + 1]);

    float4 acc = __ldg(hp + (size_t)n * 8 + p);   // self term
    int r = beg;
    while (r + 8 <= end) {
        int idx[8];
#pragma unroll
        for (int j = 0; j < 8; j++) idx[j] = __ldcs(&g_csrsrc[r + j]);
        float4 hv[8];
#pragma unroll
        for (int j = 0; j < 8; j++) hv[j] = __ldg(hp + (size_t)idx[j] * 8 + p);
        acc = add4(acc, add4(add4(add4(hv[0], hv[1]), add4(hv[2], hv[3])),
                             add4(add4(hv[4], hv[5]), add4(hv[6], hv[7]))));
        r += 8;
    }
    if (r + 4 <= end) {
        int idx[4];
#pragma unroll
        for (int j = 0; j < 4; j++) idx[j] = __ldcs(&g_csrsrc[r + j]);
        float4 hv[4];
#pragma unroll
        for (int j = 0; j < 4; j++) hv[j] = __ldg(hp + (size_t)idx[j] * 8 + p);
        acc = add4(acc, add4(add4(hv[0], hv[1]), add4(hv[2], hv[3])));
        r += 4;
    }
    for (; r < end; r++) {
        int s = __ldcs(&g_csrsrc[r]);
        acc = add4(acc, __ldg(hp + (size_t)s * 8 + p));
    }

    float dn = g_dinv[n];
    float4 xv;
    xv.x = fmaxf(fmaf(acc.x * dn, sA[4 * p + 0], sB[4 * p + 0]), 0.f);
    xv.y = fmaxf(fmaf(acc.y * dn, sA[4 * p + 1], sB[4 * p + 1]), 0.f);
    xv.z = fmaxf(fmaf(acc.z * dn, sA[4 * p + 2], sB[4 * p + 2]), 0.f);
    xv.w = fmaxf(fmaf(acc.w * dn, sA[4 * p + 3], sB[4 * p + 3]), 0.f);
    *(float4*)(xs + nl * 40 + 4 * p) = xv;
    __syncthreads();

    // GEMM: 4 output channels (4p..4p+3) for node nl
    float xrf[HH];
    {
        const float4* xrp = (const float4*)(xs + nl * 40);
#pragma unroll
        for (int q = 0; q < 8; q++) {
            float4 v = xrp[q];
            xrf[4 * q + 0] = v.x; xrf[4 * q + 1] = v.y;
            xrf[4 * q + 2] = v.z; xrf[4 * q + 3] = v.w;
        }
    }
    unsigned long long a0 = 0ULL, a1 = 0ULL;
#pragma unroll
    for (int k = 0; k < HH; k++) {
        unsigned long long xkk = pk2(xrf[k], xrf[k]);
        ulonglong2 w = Ws2[k * 8 + p];
        fma2(a0, xkk, w.x);
        fma2(a1, xkk, w.y);
    }
    unsigned long long dn2 = pk2(dn, dn);
    ((ulonglong2*)(hout + (size_t)n * HH))[p] =
        make_ulonglong2(mul2(a0, dn2), mul2(a1, dn2));
}

// ---------------- final layer: gather + BN2 + ReLU -> g_x -------------------
__global__ void __launch_bounds__(256) k_gfinal(
    const float* __restrict__ bcp,
    const float* __restrict__ gamma, const float* __restrict__ beta,
    const float* __restrict__ rmean, const float* __restrict__ rvar)
{
    __shared__ float sA[HH], sB[HH];
    int t = threadIdx.x;
    if (t < HH) {
        float sc = gamma[2 * HH + t] * rsqrtf(rvar[2 * HH + t] + EPSF);
        float sh = beta[2 * HH + t] - rmean[2 * HH + t] * sc;
        sA[t] = sc;
        sB[t] = fmaf(bcp[2 * HH + t], sc, sh);
    }
    __syncthreads();

    int tid = blockIdx.x * 256 + t;   // grid covers NN*8
    int n = tid >> 3;
    int p = tid & 7;
    const float4* hp = (const float4*)g_ha;

    int beg = __ldg(&g_rowstart[n]);
    int end = __ldg(&g_rowstart[n + 1]);

    float4 acc = __ldg(hp + (size_t)n * 8 + p);
    int r = beg;
    while (r + 8 <= end) {
        int idx[8];
#pragma unroll
        for (int j = 0; j < 8; j++) idx[j] = __ldcs(&g_csrsrc[r + j]);
        float4 hv[8];
#pragma unroll
        for (int j = 0; j < 8; j++) hv[j] = __ldg(hp + (size_t)idx[j] * 8 + p);
        acc = add4(acc, add4(add4(add4(hv[0], hv[1]), add4(hv[2], hv[3])),
                             add4(add4(hv[4], hv[5]), add4(hv[6], hv[7]))));
        r += 8;
    }
    if (r + 4 <= end) {
        int idx[4];
#pragma unroll
        for (int j = 0; j < 4; j++) idx[j] = __ldcs(&g_csrsrc[r + j]);
        float4 hv[4];
#pragma unroll
        for (int j = 0; j < 4; j++) hv[j] = __ldg(hp + (size_t)idx[j] * 8 + p);
        acc = add4(acc, add4(add4(hv[0], hv[1]), add4(hv[2], hv[3])));
        r += 4;
    }
    for (; r < end; r++) {
        int s = __ldcs(&g_csrsrc[r]);
        acc = add4(acc, __ldg(hp + (size_t)s * 8 + p));
    }

    float dn = g_dinv[n];
    float4 xv;
    xv.x = fmaxf(fmaf(acc.x * dn, sA[4 * p + 0], sB[4 * p + 0]), 0.f);
    xv.y = fmaxf(fmaf(acc.y * dn, sA[4 * p + 1], sB[4 * p + 1]), 0.f);
    xv.z = fmaxf(fmaf(acc.z * dn, sA[4 * p + 2], sB[4 * p + 2]), 0.f);
    xv.w = fmaxf(fmaf(acc.w * dn, sA[4 * p + 3], sB[4 * p + 3]), 0.f);
    ((float4*)(g_x + (size_t)n * HH))[p] = xv;
}

// ---------------- SortPool (x already BN+ReLU'd, nonneg) --------------------
__global__ void __launch_bounds__(256) k_sortpool() {
    __shared__ unsigned long long keys[CAP];
    __shared__ int ssel[KK];
    int b = blockIdx.x, t = threadIdx.x;

    int start = g_start2[b];
    int cnt = g_start2[b + 1] - start;
    int cc = min(cnt, CAP);

    for (int r = t; r < CAP; r += 256) {
        unsigned long long key = 0xFFFFFFFFFFFFFFFFull;
        if (r < cc) {
            float v = g_x[(size_t)(start + r) * HH + 31];  // nonneg
            unsigned u = (v == 0.0f) ? 0u : __float_as_uint(v);
            key = ((unsigned long long)(~u) << 32) | (unsigned)r;
        }
        keys[r] = key;
    }
    __syncthreads();

    for (int k = 2; k <= CAP; k <<= 1) {
        for (int j = k >> 1; j > 0; j >>= 1) {
            for (int base = 0; base < CAP; base += 256) {
                int i = base + t;
                int ixj = i ^ j;
                if (ixj > i) {
                    unsigned long long a = keys[i], c = keys[ixj];
                    bool up = ((i & k) == 0);
                    bool sw = up ? (a > c) : (a < c);
                    if (sw) { keys[i] = c; keys[ixj] = a; }
                }
            }
            __syncthreads();
        }
    }

    int nval = min(cc, KK);
    if (t < KK) ssel[t] = (t < nval) ? (int)(unsigned)(keys[t] & 0xFFFFFFFFu) : -1;
    __syncthreads();

    for (int idx = t; idx < KK * HH; idx += 256) {
        int k = idx >> 5, j = idx & 31;
        float v = 0.f;
        int r = ssel[k];
        if (r >= 0) v = g_x[(size_t)(start + r) * HH + j];
        g_pooled[(size_t)b * (KK * HH) + idx] = v;
    }
}

// ---------------- MLP head: block-tiled, 32 graphs/block --------------------
__global__ void __launch_bounds__(256) k_mlp(
    const float* __restrict__ W1, const float* __restrict__ b1,
    const float* __restrict__ W2, const float* __restrict__ b2,
    const float* __restrict__ W3, const float* __restrict__ b3,
    float* __restrict__ out)
{
    __shared__ float  Xs[32][33];
    __shared__ float4 Wt[32][8];
    __shared__ float  H1[32][33];
    int t = threadIdx.x;
    int tg = t >> 3, tj = t & 7;
    int g0 = blockIdx.x * 32;

    float4 accf = __ldg((const float4*)b1 + tj);
    unsigned long long a0 = pk2(accf.x, accf.y);
    unsigned long long a1 = pk2(accf.z, accf.w);

    for (int c = 0; c < 30; c++) {
        int p0 = c * 32;
        __syncthreads();
        float4 xv = __ldg((const float4*)(g_pooled + (size_t)(g0 + tg) * (KK * HH)
                                          + p0 + 4 * tj));
        Xs[tg][4 * tj + 0] = xv.x; Xs[tg][4 * tj + 1] = xv.y;
        Xs[tg][4 * tj + 2] = xv.z; Xs[tg][4 * tj + 3] = xv.w;
        Wt[tg][tj] = __ldg((const float4*)(W1 + (size_t)(p0 + tg) * 32 + 4 * tj));
        __syncthreads();
#pragma unroll
        for (int kk = 0; kk < 32; kk++) {
            float xk = Xs[tg][kk];
            unsigned long long xkk = pk2(xk, xk);
            float4 w = Wt[kk][tj];
            fma2(a0, xkk, pk2(w.x, w.y));
            fma2(a1, xkk, pk2(w.z, w.w));
        }
    }
    float r0, r1, r2, r3;
    asm("mov.b64 {%0,%1}, %2;" : "=f"(r0), "=f"(r1) : "l"(a0));
    asm("mov.b64 {%0,%1}, %2;" : "=f"(r2), "=f"(r3) : "l"(a1));
    H1[tg][4 * tj + 0] = fmaxf(r0, 0.f);
    H1[tg][4 * tj + 1] = fmaxf(r1, 0.f);
    H1[tg][4 * tj + 2] = fmaxf(r2, 0.f);
    H1[tg][4 * tj + 3] = fmaxf(r3, 0.f);
    __syncthreads();

    if (t < 32) {
        int g = t;
        float h2a[16];
#pragma unroll
        for (int m = 0; m < 16; m++) h2a[m] = b2[m];
#pragma unroll
        for (int h = 0; h < 32; h++) {
            float x = H1[g][h];
#pragma unroll
            for (int m = 0; m < 16; m++) h2a[m] = fmaf(x, W2[h * 16 + m], h2a[m]);
        }
        float o = b3[0];
#pragma unroll
        for (int m = 0; m < 16; m++) o = fmaf(fmaxf(h2a[m], 0.f), W3[m], o);
        out[g0 + g] = o;
    }
}

// ---------------- launch -----------------------------------------------------
extern "C" void kernel_launch(void* const* d_in, const int* in_sizes, int n_in,
                              void* d_out, int out_size) {
    const int*   xz    = (const int*)d_in[0];
    const int*   ei    = (const int*)d_in[1];
    const int*   batch = (const int*)d_in[2];
    const float* emb   = (const float*)d_in[3];
    const float* Wc    = (const float*)d_in[4];
    const float* bc    = (const float*)d_in[5];
    const float* gamma = (const float*)d_in[6];
    const float* beta  = (const float*)d_in[7];
    const float* rmean = (const float*)d_in[8];
    const float* rvar  = (const float*)d_in[9];
    const float* W1    = (const float*)d_in[10];
    const float* b1    = (const float*)d_in[11];
    const float* W2    = (const float*)d_in[12];
    const float* b2    = (const float*)d_in[13];
    const float* W3    = (const float*)d_in[14];
    const float* b3    = (const float*)d_in[15];
    float* out = (float*)d_out;

    const int* src = ei;
    const int* dst = ei + EE;

    k_zero  <<<NBLK, 256>>>();                 // 1
    k_degb  <<<EE / 256, 256>>>(dst, batch);   // 2
    k_scanA <<<NBLK, 256>>>();                 // 3
    k_gemm0 <<<NBLK, 256>>>(Wc, emb, xz);      // 4  (profiled slot)
    k_scanB <<<NBLK, 256>>>();                 // 5
    k_fill  <<<EE / 256, 256>>>(src, dst);     // 6
    k_gbg   <<<(NN * 8) / 256, 256>>>(0, Wc, bc, gamma, beta, rmean, rvar); // 7
    k_gbg   <<<(NN * 8) / 256, 256>>>(1, Wc, bc, gamma, beta, rmean, rvar); // 8
    k_gfinal<<<(NN * 8) / 256, 256>>>(bc, gamma, beta, rmean, rvar);        // 9
    k_sortpool<<<BB, 256>>>();                                              // 10
    k_mlp   <<<BB / 32, 256>>>(W1, b1, W2, b2, W3, b3, out);                // 11
}

// round 6
// speedup vs baseline: 1.5366x; 1.1520x over previous
#include <cuda_runtime.h>

#define NN 524288
#define EE 4194304
#define BB 4096
#define HH 32
#define KK 30
#define CAP 512
#define MAXZ1 1001
#define EPSF 1e-5f
#define NBLK 2048          // NN/256

// ---------------- scratch (device globals; no allocation allowed) ----------
__device__ int   g_deg[NN];
__device__ float g_dinv[NN];
__device__ int2  g_pack[NN];              // {xz, dinv bits}
__device__ float g_embw[MAXZ1 * HH];      // emb @ W0   (128KB, L1-resident)
__device__ float g_ha[(size_t)NN * HH];   // h' ping
__device__ float g_hb[(size_t)NN * HH];   // h' pong
__device__ float g_x[(size_t)NN * HH];    // final activations
__device__ int   g_rowstart[NN + 1];
__device__ int   g_cursor[NN];
__device__ int   g_csrsrc[EE];
__device__ int   g_bsum[NBLK];
__device__ int   g_start2[BB + 1];
__device__ float g_pooled[(size_t)BB * KK * HH];

__device__ __forceinline__ float4 add4(float4 a, float4 b) {
    return make_float4(a.x + b.x, a.y + b.y, a.z + b.z, a.w + b.w);
}
__device__ __forceinline__ float4 scale4(float4 a, float s) {
    return make_float4(a.x * s, a.y * s, a.z * s, a.w * s);
}
__device__ __forceinline__ unsigned long long pk2(float x, float y) {
    unsigned long long r;
    asm("mov.b64 %0, {%1,%2};" : "=l"(r) : "f"(x), "f"(y));
    return r;
}
__device__ __forceinline__ void fma2(unsigned long long& d, unsigned long long a,
                                     unsigned long long b) {
    asm("fma.rn.f32x2 %0, %1, %2, %0;" : "+l"(d) : "l"(a), "l"(b));
}
__device__ __forceinline__ unsigned long long mul2(unsigned long long a,
                                                   unsigned long long b) {
    unsigned long long r;
    asm("mul.rn.f32x2 %0, %1, %2;" : "=l"(r) : "l"(a), "l"(b));
    return r;
}

// ---------------- tiny precompute: embW0 = emb @ Wc[0] ----------------------
__global__ void __launch_bounds__(256) k_embw(
    const float* __restrict__ emb, const float* __restrict__ Wc)
{
    __shared__ float Ws[HH * HH];
    int t = threadIdx.x;
    for (int i = t; i < HH * HH; i += 256) Ws[i] = Wc[i];
    __syncthreads();
    int row = blockIdx.x * 8 + (t >> 5);
    int col = t & 31;
    if (row < MAXZ1) {
        const float* er = emb + (size_t)row * HH;
        float acc = 0.f;
#pragma unroll
        for (int k = 0; k < HH; k++) acc = fmaf(er[k], Ws[k * HH + col], acc);
        g_embw[row * HH + col] = acc;
    }
}

// ---------------- setup -----------------------------------------------------
__global__ void k_zero() {
    int i = blockIdx.x * 256 + threadIdx.x;
    g_deg[i] = 0;
}

// in-degree histogram + graph-boundary detection (batch is sorted)
__global__ void k_degb(const int* __restrict__ dst, const int* __restrict__ batch) {
    int i = blockIdx.x * 256 + threadIdx.x;   // grid covers EE
    atomicAdd(&g_deg[dst[i]], 1);
    if (i < NN) {
        int b1 = batch[i];
        int b0 = (i > 0) ? batch[i - 1] : -1;
        for (int b = b0 + 1; b <= b1; b++) g_start2[b] = i;
        if (i == NN - 1)
            for (int b = b1 + 1; b <= BB; b++) g_start2[b] = NN;
    }
}

// scanA: block sums of deg + dinv + pack{xz,dinv}
__global__ void k_scanA(const int* __restrict__ xz) {
    __shared__ int s[256];
    int t = threadIdx.x;
    int i = blockIdx.x * 256 + t;
    int d = g_deg[i];
    float dn = rsqrtf((float)d + 1.0f);
    g_dinv[i] = dn;
    g_pack[i] = make_int2(xz[i], __float_as_int(dn));
    s[t] = d;
    __syncthreads();
    for (int off = 128; off; off >>= 1) {
        if (t < off) s[t] += s[t + off];
        __syncthreads();
    }
    if (t == 0) g_bsum[blockIdx.x] = s[0];
}

// scanB: each block sums its bsum prefix directly, then local scan
__global__ void __launch_bounds__(256) k_scanB() {
    __shared__ int red[256];
    __shared__ int s[256];
    int b = blockIdx.x, t = threadIdx.x;
    int part = 0;
    for (int j = t; j < b; j += 256) part += g_bsum[j];
    red[t] = part;
    __syncthreads();
    for (int off = 128; off; off >>= 1) {
        if (t < off) red[t] += red[t + off];
        __syncthreads();
    }
    int base = red[0];
    int i = b * 256 + t;
    int d = g_deg[i];
    s[t] = d;
    __syncthreads();
    for (int off = 1; off < 256; off <<= 1) {
        int v = (t >= off) ? s[t - off] : 0;
        __syncthreads();
        s[t] += v;
        __syncthreads();
    }
    int excl = base + s[t] - d;
    g_rowstart[i] = excl;
    g_cursor[i] = excl;
    if (i == NN - 1) g_rowstart[NN] = EE;
}

// ---------------- CSR fill: src index only ----------------------------------
__global__ void k_fill(const int* __restrict__ src, const int* __restrict__ dst) {
    int e = blockIdx.x * 256 + threadIdx.x;   // grid covers EE
    int s = src[e], d = dst[e];
    int pos = atomicAdd(&g_cursor[d], 1);
    g_csrsrc[pos] = s;
}

// ---------------- layer 0 fused: table-gather + BN0 + ReLU + GEMM1 ----------
// h0'[m] = dinv[m] * embW0[xz[m]]   (materialized per edge from the L1 table)
// acc = sum_csr h0'[src] + h0'[n];  x = relu(BN0(acc*dinv_n));  hb = (x@W1)*dinv_n
__global__ void __launch_bounds__(256) k_gbg0(
    const float* __restrict__ Wc, const float* __restrict__ bcp,
    const float* __restrict__ gamma, const float* __restrict__ beta,
    const float* __restrict__ rmean, const float* __restrict__ rvar)
{
    __shared__ ulonglong2 Ws2[HH * 8];
    __shared__ float sA[HH], sB[HH];
    __shared__ float xs[32 * 40];
    int t = threadIdx.x;
    if (t < HH * 8) Ws2[t] = ((const ulonglong2*)(Wc + 1 * HH * HH))[t];
    if (t < HH) {
        float sc = gamma[t] * rsqrtf(rvar[t] + EPSF);
        float sh = beta[t] - rmean[t] * sc;
        sA[t] = sc;
        sB[t] = fmaf(bcp[t], sc, sh);
    }
    __syncthreads();

    int tid = blockIdx.x * 256 + t;   // grid covers NN*8
    int n = tid >> 3;
    int p = tid & 7;
    int nl = t >> 3;
    const float4* ew = (const float4*)g_embw;

    int beg = __ldg(&g_rowstart[n]);
    int end = __ldg(&g_rowstart[n + 1]);

    // self term
    int2 pks = __ldg(&g_pack[n]);
    float dn = __int_as_float(pks.y);
    float4 acc = scale4(__ldg(ew + (size_t)pks.x * 8 + p), dn);

    int r = beg;
    while (r + 8 <= end) {
        int idx[8];
#pragma unroll
        for (int j = 0; j < 8; j++) idx[j] = __ldcs(&g_csrsrc[r + j]);
        int2 pk[8];
#pragma unroll
        for (int j = 0; j < 8; j++) pk[j] = __ldg(&g_pack[idx[j]]);
        float4 hv[8];
#pragma unroll
        for (int j = 0; j < 8; j++)
            hv[j] = scale4(__ldg(ew + (size_t)pk[j].x * 8 + p),
                           __int_as_float(pk[j].y));
        acc = add4(acc, add4(add4(add4(hv[0], hv[1]), add4(hv[2], hv[3])),
                             add4(add4(hv[4], hv[5]), add4(hv[6], hv[7]))));
        r += 8;
    }
    if (r + 4 <= end) {
        int idx[4];
#pragma unroll
        for (int j = 0; j < 4; j++) idx[j] = __ldcs(&g_csrsrc[r + j]);
        int2 pk[4];
#pragma unroll
        for (int j = 0; j < 4; j++) pk[j] = __ldg(&g_pack[idx[j]]);
        float4 hv[4];
#pragma unroll
        for (int j = 0; j < 4; j++)
            hv[j] = scale4(__ldg(ew + (size_t)pk[j].x * 8 + p),
                           __int_as_float(pk[j].y));
        acc = add4(acc, add4(add4(hv[0], hv[1]), add4(hv[2], hv[3])));
        r += 4;
    }
    for (; r < end; r++) {
        int s = __ldcs(&g_csrsrc[r]);
        int2 pk = __ldg(&g_pack[s]);
        acc = add4(acc, scale4(__ldg(ew + (size_t)pk.x * 8 + p),
                               __int_as_float(pk.y)));
    }

    float4 xv;
    xv.x = fmaxf(fmaf(acc.x * dn, sA[4 * p + 0], sB[4 * p + 0]), 0.f);
    xv.y = fmaxf(fmaf(acc.y * dn, sA[4 * p + 1], sB[4 * p + 1]), 0.f);
    xv.z = fmaxf(fmaf(acc.z * dn, sA[4 * p + 2], sB[4 * p + 2]), 0.f);
    xv.w = fmaxf(fmaf(acc.w * dn, sA[4 * p + 3], sB[4 * p + 3]), 0.f);
    *(float4*)(xs + nl * 40 + 4 * p) = xv;
    __syncthreads();

    float xrf[HH];
    {
        const float4* xrp = (const float4*)(xs + nl * 40);
#pragma unroll
        for (int q = 0; q < 8; q++) {
            float4 v = xrp[q];
            xrf[4 * q + 0] = v.x; xrf[4 * q + 1] = v.y;
            xrf[4 * q + 2] = v.z; xrf[4 * q + 3] = v.w;
        }
    }
    unsigned long long a0 = 0ULL, a1 = 0ULL;
#pragma unroll
    for (int k = 0; k < HH; k++) {
        unsigned long long xkk = pk2(xrf[k], xrf[k]);
        ulonglong2 w = Ws2[k * 8 + p];
        fma2(a0, xkk, w.x);
        fma2(a1, xkk, w.y);
    }
    unsigned long long dn2 = pk2(dn, dn);
    ((ulonglong2*)(g_hb + (size_t)n * HH))[p] =
        make_ulonglong2(mul2(a0, dn2), mul2(a1, dn2));
}

// ---------------- layer 1 fused: gather(hb) + BN1 + ReLU + GEMM2 -> ha ------
__global__ void __launch_bounds__(256) k_gbg(
    const float* __restrict__ Wc, const float* __restrict__ bcp,
    const float* __restrict__ gamma, const float* __restrict__ beta,
    const float* __restrict__ rmean, const float* __restrict__ rvar)
{
    __shared__ ulonglong2 Ws2[HH * 8];
    __shared__ float sA[HH], sB[HH];
    __shared__ float xs[32 * 40];
    int t = threadIdx.x;
    if (t < HH * 8) Ws2[t] = ((const ulonglong2*)(Wc + 2 * HH * HH))[t];
    if (t < HH) {
        float sc = gamma[HH + t] * rsqrtf(rvar[HH + t] + EPSF);
        float sh = beta[HH + t] - rmean[HH + t] * sc;
        sA[t] = sc;
        sB[t] = fmaf(bcp[HH + t], sc, sh);
    }
    __syncthreads();

    int tid = blockIdx.x * 256 + t;   // grid covers NN*8
    int n = tid >> 3;
    int p = tid & 7;
    int nl = t >> 3;
    const float4* hp = (const float4*)g_hb;

    int beg = __ldg(&g_rowstart[n]);
    int end = __ldg(&g_rowstart[n + 1]);

    float4 acc = __ldg(hp + (size_t)n * 8 + p);   // self term
    int r = beg;
    while (r + 8 <= end) {
        int idx[8];
#pragma unroll
        for (int j = 0; j < 8; j++) idx[j] = __ldcs(&g_csrsrc[r + j]);
        float4 hv[8];
#pragma unroll
        for (int j = 0; j < 8; j++) hv[j] = __ldg(hp + (size_t)idx[j] * 8 + p);
        acc = add4(acc, add4(add4(add4(hv[0], hv[1]), add4(hv[2], hv[3])),
                             add4(add4(hv[4], hv[5]), add4(hv[6], hv[7]))));
        r += 8;
    }
    if (r + 4 <= end) {
        int idx[4];
#pragma unroll
        for (int j = 0; j < 4; j++) idx[j] = __ldcs(&g_csrsrc[r + j]);
        float4 hv[4];
#pragma unroll
        for (int j = 0; j < 4; j++) hv[j] = __ldg(hp + (size_t)idx[j] * 8 + p);
        acc = add4(acc, add4(add4(hv[0], hv[1]), add4(hv[2], hv[3])));
        r += 4;
    }
    for (; r < end; r++) {
        int s = __ldcs(&g_csrsrc[r]);
        acc = add4(acc, __ldg(hp + (size_t)s * 8 + p));
    }

    float dn = g_dinv[n];
    float4 xv;
    xv.x = fmaxf(fmaf(acc.x * dn, sA[4 * p + 0], sB[4 * p + 0]), 0.f);
    xv.y = fmaxf(fmaf(acc.y * dn, sA[4 * p + 1], sB[4 * p + 1]), 0.f);
    xv.z = fmaxf(fmaf(acc.z * dn, sA[4 * p + 2], sB[4 * p + 2]), 0.f);
    xv.w = fmaxf(fmaf(acc.w * dn, sA[4 * p + 3], sB[4 * p + 3]), 0.f);
    *(float4*)(xs + nl * 40 + 4 * p) = xv;
    __syncthreads();

    float xrf[HH];
    {
        const float4* xrp = (const float4*)(xs + nl * 40);
#pragma unroll
        for (int q = 0; q < 8; q++) {
            float4 v = xrp[q];
            xrf[4 * q + 0] = v.x; xrf[4 * q + 1] = v.y;
            xrf[4 * q + 2] = v.z; xrf[4 * q + 3] = v.w;
        }
    }
    unsigned long long a0 = 0ULL, a1 = 0ULL;
#pragma unroll
    for (int k = 0; k < HH; k++) {
        unsigned long long xkk = pk2(xrf[k], xrf[k]);
        ulonglong2 w = Ws2[k * 8 + p];
        fma2(a0, xkk, w.x);
        fma2(a1, xkk, w.y);
    }
    unsigned long long dn2 = pk2(dn, dn);
    ((ulonglong2*)(g_ha + (size_t)n * HH))[p] =
        make_ulonglong2(mul2(a0, dn2), mul2(a1, dn2));
}

// ---------------- final layer: gather(ha) + BN2 + ReLU -> g_x ---------------
__global__ void __launch_bounds__(256) k_gfinal(
    const float* __restrict__ bcp,
    const float* __restrict__ gamma, const float* __restrict__ beta,
    const float* __restrict__ rmean, const float* __restrict__ rvar)
{
    __shared__ float sA[HH], sB[HH];
    int t = threadIdx.x;
    if (t < HH) {
        float sc = gamma[2 * HH + t] * rsqrtf(rvar[2 * HH + t] + EPSF);
        float sh = beta[2 * HH + t] - rmean[2 * HH + t] * sc;
        sA[t] = sc;
        sB[t] = fmaf(bcp[2 * HH + t], sc, sh);
    }
    __syncthreads();

    int tid = blockIdx.x * 256 + t;   // grid covers NN*8
    int n = tid >> 3;
    int p = tid & 7;
    const float4* hp = (const float4*)g_ha;

    int beg = __ldg(&g_rowstart[n]);
    int end = __ldg(&g_rowstart[n + 1]);

    float4 acc = __ldg(hp + (size_t)n * 8 + p);
    int r = beg;
    while (r + 8 <= end) {
        int idx[8];
#pragma unroll
        for (int j = 0; j < 8; j++) idx[j] = __ldcs(&g_csrsrc[r + j]);
        float4 hv[8];
#pragma unroll
        for (int j = 0; j < 8; j++) hv[j] = __ldg(hp + (size_t)idx[j] * 8 + p);
        acc = add4(acc, add4(add4(add4(hv[0], hv[1]), add4(hv[2], hv[3])),
                             add4(add4(hv[4], hv[5]), add4(hv[6], hv[7]))));
        r += 8;
    }
    if (r + 4 <= end) {
        int idx[4];
#pragma unroll
        for (int j = 0; j < 4; j++) idx[j] = __ldcs(&g_csrsrc[r + j]);
        float4 hv[4];
#pragma unroll
        for (int j = 0; j < 4; j++) hv[j] = __ldg(hp + (size_t)idx[j] * 8 + p);
        acc = add4(acc, add4(add4(hv[0], hv[1]), add4(hv[2], hv[3])));
        r += 4;
    }
    for (; r < end; r++) {
        int s = __ldcs(&g_csrsrc[r]);
        acc = add4(acc, __ldg(hp + (size_t)s * 8 + p));
    }

    float dn = g_dinv[n];
    float4 xv;
    xv.x = fmaxf(fmaf(acc.x * dn, sA[4 * p + 0], sB[4 * p + 0]), 0.f);
    xv.y = fmaxf(fmaf(acc.y * dn, sA[4 * p + 1], sB[4 * p + 1]), 0.f);
    xv.z = fmaxf(fmaf(acc.z * dn, sA[4 * p + 2], sB[4 * p + 2]), 0.f);
    xv.w = fmaxf(fmaf(acc.w * dn, sA[4 * p + 3], sB[4 * p + 3]), 0.f);
    ((float4*)(g_x + (size_t)n * HH))[p] = xv;
}

// ---------------- SortPool (x already BN+ReLU'd, nonneg) --------------------
__global__ void __launch_bounds__(256) k_sortpool() {
    __shared__ unsigned long long keys[CAP];
    __shared__ int ssel[KK];
    int b = blockIdx.x, t = threadIdx.x;

    int start = g_start2[b];
    int cnt = g_start2[b + 1] - start;
    int cc = min(cnt, CAP);

    for (int r = t; r < CAP; r += 256) {
        unsigned long long key = 0xFFFFFFFFFFFFFFFFull;
        if (r < cc) {
            float v = g_x[(size_t)(start + r) * HH + 31];  // nonneg
            unsigned u = (v == 0.0f) ? 0u : __float_as_uint(v);
            key = ((unsigned long long)(~u) << 32) | (unsigned)r;
        }
        keys[r] = key;
    }
    __syncthreads();

    for (int k = 2; k <= CAP; k <<= 1) {
        for (int j = k >> 1; j > 0; j >>= 1) {
            for (int base = 0; base < CAP; base += 256) {
                int i = base + t;
                int ixj = i ^ j;
                if (ixj > i) {
                    unsigned long long a = keys[i], c = keys[ixj];
                    bool up = ((i & k) == 0);
                    bool sw = up ? (a > c) : (a < c);
                    if (sw) { keys[i] = c; keys[ixj] = a; }
                }
            }
            __syncthreads();
        }
    }

    int nval = min(cc, KK);
    if (t < KK) ssel[t] = (t < nval) ? (int)(unsigned)(keys[t] & 0xFFFFFFFFu) : -1;
    __syncthreads();

    for (int idx = t; idx < KK * HH; idx += 256) {
        int k = idx >> 5, j = idx & 31;
        float v = 0.f;
        int r = ssel[k];
        if (r >= 0) v = g_x[(size_t)(start + r) * HH + j];
        g_pooled[(size_t)b * (KK * HH) + idx] = v;
    }
}

// ---------------- MLP head: block-tiled, 32 graphs/block --------------------
__global__ void __launch_bounds__(256) k_mlp(
    const float* __restrict__ W1, const float* __restrict__ b1,
    const float* __restrict__ W2, const float* __restrict__ b2,
    const float* __restrict__ W3, const float* __restrict__ b3,
    float* __restrict__ out)
{
    __shared__ float  Xs[32][33];
    __shared__ float4 Wt[32][8];
    __shared__ float  H1[32][33];
    int t = threadIdx.x;
    int tg = t >> 3, tj = t & 7;
    int g0 = blockIdx.x * 32;

    float4 accf = __ldg((const float4*)b1 + tj);
    unsigned long long a0 = pk2(accf.x, accf.y);
    unsigned long long a1 = pk2(accf.z, accf.w);

    for (int c = 0; c < 30; c++) {
        int p0 = c * 32;
        __syncthreads();
        float4 xv = __ldg((const float4*)(g_pooled + (size_t)(g0 + tg) * (KK * HH)
                                          + p0 + 4 * tj));
        Xs[tg][4 * tj + 0] = xv.x; Xs[tg][4 * tj + 1] = xv.y;
        Xs[tg][4 * tj + 2] = xv.z; Xs[tg][4 * tj + 3] = xv.w;
        Wt[tg][tj] = __ldg((const float4*)(W1 + (size_t)(p0 + tg) * 32 + 4 * tj));
        __syncthreads();
#pragma unroll
        for (int kk = 0; kk < 32; kk++) {
            float xk = Xs[tg][kk];
            unsigned long long xkk = pk2(xk, xk);
            float4 w = Wt[kk][tj];
            fma2(a0, xkk, pk2(w.x, w.y));
            fma2(a1, xkk, pk2(w.z, w.w));
        }
    }
    float r0, r1, r2, r3;
    asm("mov.b64 {%0,%1}, %2;" : "=f"(r0), "=f"(r1) : "l"(a0));
    asm("mov.b64 {%0,%1}, %2;" : "=f"(r2), "=f"(r3) : "l"(a1));
    H1[tg][4 * tj + 0] = fmaxf(r0, 0.f);
    H1[tg][4 * tj + 1] = fmaxf(r1, 0.f);
    H1[tg][4 * tj + 2] = fmaxf(r2, 0.f);
    H1[tg][4 * tj + 3] = fmaxf(r3, 0.f);
    __syncthreads();

    if (t < 32) {
        int g = t;
        float h2a[16];
#pragma unroll
        for (int m = 0; m < 16; m++) h2a[m] = b2[m];
#pragma unroll
        for (int h = 0; h < 32; h++) {
            float x = H1[g][h];
#pragma unroll
            for (int m = 0; m < 16; m++) h2a[m] = fmaf(x, W2[h * 16 + m], h2a[m]);
        }
        float o = b3[0];
#pragma unroll
        for (int m = 0; m < 16; m++) o = fmaf(fmaxf(h2a[m], 0.f), W3[m], o);
        out[g0 + g] = o;
    }
}

// ---------------- launch -----------------------------------------------------
extern "C" void kernel_launch(void* const* d_in, const int* in_sizes, int n_in,
                              void* d_out, int out_size) {
    const int*   xz    = (const int*)d_in[0];
    const int*   ei    = (const int*)d_in[1];
    const int*   batch = (const int*)d_in[2];
    const float* emb   = (const float*)d_in[3];
    const float* Wc    = (const float*)d_in[4];
    const float* bc    = (const float*)d_in[5];
    const float* gamma = (const float*)d_in[6];
    const float* beta  = (const float*)d_in[7];
    const float* rmean = (const float*)d_in[8];
    const float* rvar  = (const float*)d_in[9];
    const float* W1    = (const float*)d_in[10];
    const float* b1    = (const float*)d_in[11];
    const float* W2    = (const float*)d_in[12];
    const float* b2    = (const float*)d_in[13];
    const float* W3    = (const float*)d_in[14];
    const float* b3    = (const float*)d_in[15];
    float* out = (float*)d_out;

    const int* src = ei;
    const int* dst = ei + EE;

    k_embw  <<<(MAXZ1 + 7) / 8, 256>>>(emb, Wc);                        // 1
    k_zero  <<<NBLK, 256>>>();                                          // 2
    k_degb  <<<EE / 256, 256>>>(dst, batch);                            // 3
    k_scanA <<<NBLK, 256>>>(xz);                                        // 4 (profiled)
    k_scanB <<<NBLK, 256>>>();                                          // 5
    k_fill  <<<EE / 256, 256>>>(src, dst);                              // 6
    k_gbg0  <<<(NN * 8) / 256, 256>>>(Wc, bc, gamma, beta, rmean, rvar);// 7
    k_gbg   <<<(NN * 8) / 256, 256>>>(Wc, bc, gamma, beta, rmean, rvar);// 8
    k_gfinal<<<(NN * 8) / 256, 256>>>(bc, gamma, beta, rmean, rvar);    // 9
    k_sortpool<<<BB, 256>>>();                                          // 10
    k_mlp   <<<BB / 32, 256>>>(W1, b1, W2, b2, W3, b3, out);            // 11
}